// round 3
// baseline (speedup 1.0000x reference)
#include <cuda_runtime.h>
#include <cuda_bf16.h>
#include <math.h>

#define MAXN 200000
#define MAXB 2
#define IMG_H 300
#define IMG_W 400
#define HW (IMG_H * IMG_W)
#define DFEAT 256
#define HID 256

// ---------------- scratch (static device globals; no allocation) ----------------
__device__ float g_F[(size_t)MAXN * HID];        // feat @ W1[0:256,:]  (~205 MB)
__device__ float g_vdir[(size_t)MAXB * MAXN * 3];
__device__ float g_wts[(size_t)MAXB * MAXN];
__device__ int   g_idx[(size_t)MAXB * MAXN];
__device__ float g_num[(size_t)MAXB * HW * 3];
__device__ float g_den[(size_t)MAXB * HW];
__device__ float g_pinv[MAXB * 16];

__device__ __forceinline__ float sigmoidf_(float x) {
    return 1.0f / (1.0f + expf(-x));
}

// No-FMA dot product: ((a0*x0 + a1*x1) + a2*x2), each op separately rounded.
// Matches XLA fusion codegen (fp contraction disabled).
__device__ __forceinline__ float dot3_nofma(float a0, float a1, float a2,
                                            float x0, float x1, float x2) {
    float t0 = __fmul_rn(a0, x0);
    float t1 = __fmul_rn(a1, x1);
    float t2 = __fmul_rn(a2, x2);
    return __fadd_rn(__fadd_rn(t0, t1), t2);
}

// ---------------- 1) 4x4 pose inverse (Gaussian elimination w/ partial pivot) ---
__global__ void prep_kernel(const float* __restrict__ pose, int B) {
    int b = threadIdx.x;
    if (b >= B) return;
    float a[4][8];
    for (int r = 0; r < 4; r++)
        for (int c = 0; c < 4; c++) {
            a[r][c] = pose[b * 16 + r * 4 + c];
            a[r][4 + c] = (r == c) ? 1.0f : 0.0f;
        }
    for (int col = 0; col < 4; col++) {
        int piv = col;
        for (int r = col + 1; r < 4; r++)
            if (fabsf(a[r][col]) > fabsf(a[piv][col])) piv = r;
        if (piv != col)
            for (int c = 0; c < 8; c++) { float t = a[col][c]; a[col][c] = a[piv][c]; a[piv][c] = t; }
        float d = 1.0f / a[col][col];
        for (int c = 0; c < 8; c++) a[col][c] *= d;
        for (int r = 0; r < 4; r++) {
            if (r == col) continue;
            float f = a[r][col];
            for (int c = 0; c < 8; c++) a[r][c] -= f * a[col][c];
        }
    }
    for (int r = 0; r < 4; r++)
        for (int c = 0; c < 4; c++)
            g_pinv[b * 16 + r * 4 + c] = a[r][4 + c];
}

// ---------------- 2) zero accumulators ----------------
__global__ void zero_kernel(int B) {
    int i = blockIdx.x * blockDim.x + threadIdx.x;
    int n3 = B * HW * 3;
    int n1 = B * HW;
    if (i < n3) g_num[i] = 0.0f;
    if (i < n1) g_den[i] = 0.0f;
}

// ---------------- 3) geometry: project, validity, vdir, opacity ----------------
__global__ void geom_kernel(const float* __restrict__ vert_pos,
                            const float* __restrict__ pose,
                            const float* __restrict__ intr,
                            const float* __restrict__ opy,
                            int N, int B) {
    int i = blockIdx.x * blockDim.x + threadIdx.x;
    if (i >= B * N) return;
    int b = i / N, n = i - b * N;

    float px = vert_pos[n], py = vert_pos[N + n], pz = vert_pos[2 * N + n];
    const float* P = pose + b * 16;
    // pose @ [px,py,pz,1]: no-FMA mul/add chain, separately rounded
    float x = __fadd_rn(dot3_nofma(P[0], P[1], P[2],  px, py, pz), __fmul_rn(P[3],  1.0f));
    float y = __fadd_rn(dot3_nofma(P[4], P[5], P[6],  px, py, pz), __fmul_rn(P[7],  1.0f));
    float z = __fadd_rn(dot3_nofma(P[8], P[9], P[10], px, py, pz), __fmul_rn(P[11], 1.0f));

    const float* Km = intr + b * 9;
    float u_ = dot3_nofma(Km[0], Km[1], Km[2], x, y, z);
    float v_ = dot3_nofma(Km[3], Km[4], Km[5], x, y, z);
    float w_ = dot3_nofma(Km[6], Km[7], Km[8], x, y, z);

    bool em = fabsf(w_) < 0.01f;
    float zs = em ? 0.01f : w_;
    float su = em ? -1e6f : __fdiv_rn(u_, zs);   // IEEE division
    float sv = em ? -1e6f : __fdiv_rn(v_, zs);
    float sz = em ? -1e6f : zs;

    float inorm = rsqrtf(x * x + y * y + z * z);
    float nx = x * inorm, ny = y * inorm, nz = z * inorm;
    const float* Pi = g_pinv + b * 16;
    // vh[3] = 0 so the translation column drops out (smooth quantity, any order)
    g_vdir[(size_t)i * 3 + 0] = dot3_nofma(Pi[0], Pi[1], Pi[2],  nx, ny, nz);
    g_vdir[(size_t)i * 3 + 1] = dot3_nofma(Pi[4], Pi[5], Pi[6],  nx, ny, nz);
    g_vdir[(size_t)i * 3 + 2] = dot3_nofma(Pi[8], Pi[9], Pi[10], nx, ny, nz);

    int ix = (int)rintf(su);     // round-half-even, matches jnp.round
    int iy = (int)rintf(sv);
    bool valid = (ix >= 0) && (ix < IMG_W) && (iy >= 0) && (iy < IMG_H) && (sz >= 1.0f);
    g_idx[i] = valid ? iy * IMG_W + ix : HW;
    float op = sigmoidf_(opy[n]);
    op = fminf(fmaxf(op, 0.0f), 1.0f);
    g_wts[i] = valid ? op : 0.0f;
}

// ---------------- 4) SGEMM: F = feat(N x 256) @ W1[0:256,:] (256 x 256) --------
// 128x128 block tile, 16 K-slice, 8x8 per thread, 256 threads.
__global__ __launch_bounds__(256) void gemm_kernel(const float* __restrict__ A,
                                                   const float* __restrict__ Bw,
                                                   int M) {
    __shared__ float As[16][128];
    __shared__ float Bs[16][128];

    int rowBase = blockIdx.x * 128;
    int colBase = blockIdx.y * 128;
    int tid = threadIdx.x;
    int tx = tid & 15, ty = tid >> 4;

    float acc[8][8];
#pragma unroll
    for (int m = 0; m < 8; m++)
#pragma unroll
        for (int n = 0; n < 8; n++) acc[m][n] = 0.0f;

    int a_r = tid >> 2;          // 0..63
    int a_c = (tid & 3) << 2;    // 0,4,8,12
    int b_r = tid >> 5;          // 0..7
    int b_c = (tid & 31) << 2;   // 0..124

    for (int k0 = 0; k0 < DFEAT; k0 += 16) {
#pragma unroll
        for (int rr = 0; rr < 2; rr++) {
            int gr = rowBase + a_r + rr * 64;
            float4 av = (gr < M)
                ? *(const float4*)(A + (size_t)gr * DFEAT + k0 + a_c)
                : make_float4(0.f, 0.f, 0.f, 0.f);
            As[a_c + 0][a_r + rr * 64] = av.x;
            As[a_c + 1][a_r + rr * 64] = av.y;
            As[a_c + 2][a_r + rr * 64] = av.z;
            As[a_c + 3][a_r + rr * 64] = av.w;
        }
#pragma unroll
        for (int rr = 0; rr < 2; rr++) {
            int kr = b_r + rr * 8;
            *(float4*)&Bs[kr][b_c] =
                *(const float4*)(Bw + (size_t)(k0 + kr) * HID + colBase + b_c);
        }
        __syncthreads();

#pragma unroll
        for (int k = 0; k < 16; k++) {
            float4 ra0 = *(const float4*)&As[k][ty * 8];
            float4 ra1 = *(const float4*)&As[k][ty * 8 + 4];
            float4 rb0 = *(const float4*)&Bs[k][tx * 8];
            float4 rb1 = *(const float4*)&Bs[k][tx * 8 + 4];
            float ra[8] = {ra0.x, ra0.y, ra0.z, ra0.w, ra1.x, ra1.y, ra1.z, ra1.w};
            float rb[8] = {rb0.x, rb0.y, rb0.z, rb0.w, rb1.x, rb1.y, rb1.z, rb1.w};
#pragma unroll
            for (int m = 0; m < 8; m++)
#pragma unroll
                for (int n = 0; n < 8; n++) acc[m][n] = fmaf(ra[m], rb[n], acc[m][n]);
        }
        __syncthreads();
    }

#pragma unroll
    for (int m = 0; m < 8; m++) {
        int gr = rowBase + ty * 8 + m;
        if (gr >= M) continue;
        float* dst = g_F + (size_t)gr * HID + colBase + tx * 8;
        *(float4*)dst       = make_float4(acc[m][0], acc[m][1], acc[m][2], acc[m][3]);
        *(float4*)(dst + 4) = make_float4(acc[m][4], acc[m][5], acc[m][6], acc[m][7]);
    }
}

// ---------------- 5) epilogue: rank-3 correction + relu + W2 + sigmoid + scatter
// one warp per (b, n)
__global__ void mlp_scatter_kernel(const float* __restrict__ W1,
                                   const float* __restrict__ b1,
                                   const float* __restrict__ W2,
                                   const float* __restrict__ b2,
                                   int N, int B) {
    int gwid = (blockIdx.x * blockDim.x + threadIdx.x) >> 5;
    int lane = threadIdx.x & 31;
    if (gwid >= B * N) return;
    int b = gwid / N, n = gwid - b * N;

    const float* Frow = g_F + (size_t)n * HID;
    float vd0 = g_vdir[(size_t)gwid * 3 + 0];
    float vd1 = g_vdir[(size_t)gwid * 3 + 1];
    float vd2 = g_vdir[(size_t)gwid * 3 + 2];
    const float* w1v0 = W1 + (size_t)DFEAT * HID;          // row 256
    const float* w1v1 = W1 + (size_t)(DFEAT + 1) * HID;    // row 257
    const float* w1v2 = W1 + (size_t)(DFEAT + 2) * HID;    // row 258

    float a0 = 0.f, a1 = 0.f, a2 = 0.f;
#pragma unroll
    for (int j = lane; j < HID; j += 32) {
        float h = Frow[j] + vd0 * w1v0[j] + vd1 * w1v1[j] + vd2 * w1v2[j] + b1[j];
        h = fmaxf(h, 0.0f);
        a0 = fmaf(h, W2[j * 3 + 0], a0);
        a1 = fmaf(h, W2[j * 3 + 1], a1);
        a2 = fmaf(h, W2[j * 3 + 2], a2);
    }
#pragma unroll
    for (int off = 16; off; off >>= 1) {
        a0 += __shfl_down_sync(0xFFFFFFFFu, a0, off);
        a1 += __shfl_down_sync(0xFFFFFFFFu, a1, off);
        a2 += __shfl_down_sync(0xFFFFFFFFu, a2, off);
    }
    if (lane == 0) {
        int id = g_idx[gwid];
        if (id < HW) {
            float w = g_wts[gwid];
            float r0 = sigmoidf_(a0 + b2[0]);
            float r1 = sigmoidf_(a1 + b2[1]);
            float r2 = sigmoidf_(a2 + b2[2]);
            size_t base = ((size_t)b * HW + id);
            atomicAdd(&g_num[base * 3 + 0], w * r0);
            atomicAdd(&g_num[base * 3 + 1], w * r1);
            atomicAdd(&g_num[base * 3 + 2], w * r2);
            atomicAdd(&g_den[base], w);
        }
    }
}

// ---------------- 6) composite -> output (B, 3, H, W) ----------------
__global__ void composite_kernel(const float* __restrict__ bkg,
                                 float* __restrict__ out, int B) {
    int i = blockIdx.x * blockDim.x + threadIdx.x;
    if (i >= B * HW) return;
    int b = i / HW, p = i - b * HW;
    float d = g_den[i];
    float alpha = 1.0f - expf(-d);
    float inv = __fdiv_rn(1.0f, d + 1e-8f);
#pragma unroll
    for (int c = 0; c < 3; c++) {
        float fg = g_num[(size_t)i * 3 + c] * inv;
        out[((size_t)b * 3 + c) * HW + p] = fg * alpha + bkg[c] * (1.0f - alpha);
    }
}

// ---------------- launch ----------------
extern "C" void kernel_launch(void* const* d_in, const int* in_sizes, int n_in,
                              void* d_out, int out_size) {
    const float* vert_pos = (const float*)d_in[0];
    // d_in[1] = ref_images (unused by the reference output)
    const float* pose = (const float*)d_in[2];
    const float* intr = (const float*)d_in[3];
    const float* feat = (const float*)d_in[4];
    const float* opy  = (const float*)d_in[5];
    const float* W1   = (const float*)d_in[6];
    const float* b1   = (const float*)d_in[7];
    const float* W2   = (const float*)d_in[8];
    const float* b2   = (const float*)d_in[9];
    const float* bkg  = (const float*)d_in[10];
    float* out = (float*)d_out;

    int N = in_sizes[0] / 3;
    int B = in_sizes[2] / 16;
    if (N > MAXN) N = MAXN;
    if (B > MAXB) B = MAXB;

    prep_kernel<<<1, 32>>>(pose, B);
    zero_kernel<<<(B * HW * 3 + 255) / 256, 256>>>(B);
    geom_kernel<<<(B * N + 255) / 256, 256>>>(vert_pos, pose, intr, opy, N, B);

    dim3 gemm_grid((N + 127) / 128, HID / 128);
    gemm_kernel<<<gemm_grid, 256>>>(feat, W1, N);

    int nwarps = B * N;
    mlp_scatter_kernel<<<(nwarps + 7) / 8, 256>>>(W1, b1, W2, b2, N, B);

    composite_kernel<<<(B * HW + 255) / 256, 256>>>(bkg, out, B);
}

// round 6
// speedup vs baseline: 2.2953x; 2.2953x over previous
#include <cuda_runtime.h>
#include <cuda_bf16.h>
#include <math.h>
#include <cstdint>

#define MAXN 200000
#define MAXB 2
#define IMG_H 300
#define IMG_W 400
#define HW (IMG_H * IMG_W)
#define DFEAT 256
#define HID 256

// ---------------- scratch (static device globals; no allocation) ----------------
__device__ float g_vdir[(size_t)MAXB * MAXN * 3];
__device__ float g_wts[(size_t)MAXB * MAXN];
__device__ int   g_idx[(size_t)MAXB * MAXN];
__device__ float g_num[(size_t)MAXB * HW * 3];
__device__ float g_den[(size_t)MAXB * HW];
__device__ float g_pinv[MAXB * 16];
__device__ __nv_bfloat16 g_W1T[DFEAT * HID];   // W1T[n][k] = W1[k][n], bf16, K-major

__device__ __forceinline__ float sigmoidf_(float x) {
    return 1.0f / (1.0f + expf(-x));
}

// No-FMA dot product: ((a0*x0 + a1*x1) + a2*x2), each op separately rounded.
// Matches XLA fusion codegen (fp contraction disabled). DO NOT TOUCH.
__device__ __forceinline__ float dot3_nofma(float a0, float a1, float a2,
                                            float x0, float x1, float x2) {
    float t0 = __fmul_rn(a0, x0);
    float t1 = __fmul_rn(a1, x1);
    float t2 = __fmul_rn(a2, x2);
    return __fadd_rn(__fadd_rn(t0, t1), t2);
}

__device__ __forceinline__ uint32_t smem_to_u32(const void* p) {
    uint32_t a;
    asm("{ .reg .u64 t; cvta.to.shared.u64 t, %1; cvt.u32.u64 %0, t; }" : "=r"(a) : "l"(p));
    return a;
}

// ---------------- 1) 4x4 pose inverse ----------------
__global__ void prep_kernel(const float* __restrict__ pose, int B) {
    int b = threadIdx.x;
    if (b >= B) return;
    float a[4][8];
    for (int r = 0; r < 4; r++)
        for (int c = 0; c < 4; c++) {
            a[r][c] = pose[b * 16 + r * 4 + c];
            a[r][4 + c] = (r == c) ? 1.0f : 0.0f;
        }
    for (int col = 0; col < 4; col++) {
        int piv = col;
        for (int r = col + 1; r < 4; r++)
            if (fabsf(a[r][col]) > fabsf(a[piv][col])) piv = r;
        if (piv != col)
            for (int c = 0; c < 8; c++) { float t = a[col][c]; a[col][c] = a[piv][c]; a[piv][c] = t; }
        float d = 1.0f / a[col][col];
        for (int c = 0; c < 8; c++) a[col][c] *= d;
        for (int r = 0; r < 4; r++) {
            if (r == col) continue;
            float f = a[r][col];
            for (int c = 0; c < 8; c++) a[r][c] -= f * a[col][c];
        }
    }
    for (int r = 0; r < 4; r++)
        for (int c = 0; c < 4; c++)
            g_pinv[b * 16 + r * 4 + c] = a[r][4 + c];
}

// ---------------- 2) zero accumulators ----------------
__global__ void zero_kernel(int B) {
    int i = blockIdx.x * blockDim.x + threadIdx.x;
    int n3 = B * HW * 3;
    int n1 = B * HW;
    if (i < n3) g_num[i] = 0.0f;
    if (i < n1) g_den[i] = 0.0f;
}

// ---------------- 2b) W1[0:256] -> bf16 transposed (K-major) ----------------
__global__ void convert_w1_kernel(const float* __restrict__ W1) {
    int i = blockIdx.x * blockDim.x + threadIdx.x;
    if (i >= DFEAT * HID) return;
    int k = i >> 8, n = i & 255;                       // read coalesced over n
    g_W1T[n * DFEAT + k] = __float2bfloat16(W1[k * HID + n]);
}

// ---------------- 3) geometry (exact arithmetic — passes at 9e-8) ----------------
__global__ void geom_kernel(const float* __restrict__ vert_pos,
                            const float* __restrict__ pose,
                            const float* __restrict__ intr,
                            const float* __restrict__ opy,
                            int N, int B) {
    int i = blockIdx.x * blockDim.x + threadIdx.x;
    if (i >= B * N) return;
    int b = i / N, n = i - b * N;

    float px = vert_pos[n], py = vert_pos[N + n], pz = vert_pos[2 * N + n];
    const float* P = pose + b * 16;
    float x = __fadd_rn(dot3_nofma(P[0], P[1], P[2],  px, py, pz), __fmul_rn(P[3],  1.0f));
    float y = __fadd_rn(dot3_nofma(P[4], P[5], P[6],  px, py, pz), __fmul_rn(P[7],  1.0f));
    float z = __fadd_rn(dot3_nofma(P[8], P[9], P[10], px, py, pz), __fmul_rn(P[11], 1.0f));

    const float* Km = intr + b * 9;
    float u_ = dot3_nofma(Km[0], Km[1], Km[2], x, y, z);
    float v_ = dot3_nofma(Km[3], Km[4], Km[5], x, y, z);
    float w_ = dot3_nofma(Km[6], Km[7], Km[8], x, y, z);

    bool em = fabsf(w_) < 0.01f;
    float zs = em ? 0.01f : w_;
    float su = em ? -1e6f : __fdiv_rn(u_, zs);
    float sv = em ? -1e6f : __fdiv_rn(v_, zs);
    float sz = em ? -1e6f : zs;

    float inorm = rsqrtf(x * x + y * y + z * z);
    float nx = x * inorm, ny = y * inorm, nz = z * inorm;
    const float* Pi = g_pinv + b * 16;
    g_vdir[(size_t)i * 3 + 0] = dot3_nofma(Pi[0], Pi[1], Pi[2],  nx, ny, nz);
    g_vdir[(size_t)i * 3 + 1] = dot3_nofma(Pi[4], Pi[5], Pi[6],  nx, ny, nz);
    g_vdir[(size_t)i * 3 + 2] = dot3_nofma(Pi[8], Pi[9], Pi[10], nx, ny, nz);

    int ix = (int)rintf(su);
    int iy = (int)rintf(sv);
    bool valid = (ix >= 0) && (ix < IMG_W) && (iy >= 0) && (iy < IMG_H) && (sz >= 1.0f);
    g_idx[i] = valid ? iy * IMG_W + ix : HW;
    float op = sigmoidf_(opy[n]);
    op = fminf(fmaxf(op, 0.0f), 1.0f);
    g_wts[i] = valid ? op : 0.0f;
}

// ================= 4) fused HMMA GEMM + MLP epilogue + scatter =================
// CTA: 128 points x N=256 hidden x K=256, 512 threads (16 warps, 4x4 warp grid).
// Warp tile 32x64 = 2(m) x 8(n) mma.m16n8k16 per K-step, 16 K-steps.
// SMEM: A 64KB (bf16 swizzled) + B 128KB (bf16 swizzled) + tables 7KB.
// After MMA: H (128x259 fp32, reuses A/B space) -> per-point epilogue + scatter.
#define SM_A    0
#define SM_B    (128 * 512)                       // 65536
#define SM_TAB  (SM_B + 256 * 512)                // 196608
#define SM_TOTAL (SM_TAB + (256 + 768 + 768) * 4) // 203776
#define H_STRIDE 259

__device__ __forceinline__ void ldmatrix_x4(uint32_t* r, uint32_t addr) {
    asm volatile("ldmatrix.sync.aligned.m8n8.x4.shared.b16 {%0,%1,%2,%3}, [%4];"
                 : "=r"(r[0]), "=r"(r[1]), "=r"(r[2]), "=r"(r[3]) : "r"(addr));
}
__device__ __forceinline__ void mma_bf16(float* d, const uint32_t* a, const uint32_t* b) {
    asm volatile(
        "mma.sync.aligned.m16n8k16.row.col.f32.bf16.bf16.f32 "
        "{%0,%1,%2,%3}, {%4,%5,%6,%7}, {%8,%9}, {%0,%1,%2,%3};"
        : "+f"(d[0]), "+f"(d[1]), "+f"(d[2]), "+f"(d[3])
        : "r"(a[0]), "r"(a[1]), "r"(a[2]), "r"(a[3]), "r"(b[0]), "r"(b[1]));
}

__global__ __launch_bounds__(512, 1) void fused_gemm_kernel(
    const float* __restrict__ feat,
    const float* __restrict__ W1,
    const float* __restrict__ b1g,
    const float* __restrict__ W2g,
    const float* __restrict__ b2g,
    int Npts, int B)
{
    extern __shared__ char smem[];
    uint32_t smem_u = smem_to_u32(smem);
    int tid = threadIdx.x;
    int wid = tid >> 5;
    int lane = tid & 31;
    int rowBase = blockIdx.x * 128;

    float* b1s = (float*)(smem + SM_TAB);        // [256]
    float* w1v = b1s + 256;                      // [3*256]
    float* W2s = w1v + 768;                      // [768]: W2s[c*256+j] = W2[j][c]

    // ---- load A: 128 rows x 256 fp32 -> bf16 swizzled (16B-chunk XOR) ----
    for (int it = tid; it < 8192; it += 512) {
        int row = it >> 6;
        int c4 = (it & 63) << 2;                 // fp32/bf16 col, multiple of 4
        int gr = rowBase + row;
        float4 v = (gr < Npts) ? *(const float4*)(feat + (size_t)gr * DFEAT + c4)
                               : make_float4(0.f, 0.f, 0.f, 0.f);
        __nv_bfloat162 p0 = __floats2bfloat162_rn(v.x, v.y);
        __nv_bfloat162 p1 = __floats2bfloat162_rn(v.z, v.w);
        uint32_t off = (uint32_t)row * 512
                     + (uint32_t)(((c4 >> 3) ^ (row & 7)) << 4)
                     + (uint32_t)((c4 & 4) << 1);
        *(__nv_bfloat162*)(smem + SM_A + off)     = p0;
        *(__nv_bfloat162*)(smem + SM_A + off + 4) = p1;
    }

    // ---- load B: g_W1T 256 rows(n) x 256 bf16(k), uint4 = 8 elems ----
    for (int it = tid; it < 8192; it += 512) {
        int n = it >> 5;
        int chunk = it & 31;                     // 16B chunk = 8 bf16
        uint4 v = *(const uint4*)(g_W1T + (size_t)n * DFEAT + (chunk << 3));
        uint32_t off = (uint32_t)n * 512 + (uint32_t)((chunk ^ (n & 7)) << 4);
        *(uint4*)(smem + SM_B + off) = v;
    }

    // ---- epilogue tables ----
    if (tid < 256) {
        b1s[tid]       = b1g[tid];
        w1v[tid]       = W1[(size_t)DFEAT * HID + tid];
        w1v[256 + tid] = W1[(size_t)(DFEAT + 1) * HID + tid];
        w1v[512 + tid] = W1[(size_t)(DFEAT + 2) * HID + tid];
    } else if (tid < 512) {
        int j = tid - 256;
        // FIX (round-5 bug): W2 is [HID,3] row-major. Stage transposed so
        // channel c lives at W2s[c*256 + j] = W2[j*3 + c].
        W2s[j]       = W2g[j * 3 + 0];
        W2s[256 + j] = W2g[j * 3 + 1];
        W2s[512 + j] = W2g[j * 3 + 2];
    }
    __syncthreads();

    // ---- warp tiling ----
    int warpRow = (wid >> 2) * 32;               // 0,32,64,96
    int warpCol = (wid & 3) * 64;                // 0,64,128,192

    float acc[2][8][4];
#pragma unroll
    for (int mt = 0; mt < 2; mt++)
#pragma unroll
        for (int nt = 0; nt < 8; nt++)
#pragma unroll
            for (int e = 0; e < 4; e++) acc[mt][nt][e] = 0.0f;

    // ldmatrix lane addressing (canonical CUTLASS patterns)
    int a_roff = (lane < 16) ? lane : (lane - 16);
    int a_cadd = (lane < 16) ? 0 : 1;            // +8 bf16 = +1 chunk
    uint32_t aBase[2]; int aR7[2];
#pragma unroll
    for (int mt = 0; mt < 2; mt++) {
        int r = warpRow + mt * 16 + a_roff;
        aBase[mt] = smem_u + SM_A + (uint32_t)r * 512;
        aR7[mt] = r & 7;
    }
    int b_noff = (lane & 7) + ((lane >= 16) ? 8 : 0);
    int b_cadd = (lane >> 3) & 1;
    uint32_t bBase[4]; int bR7[4];
#pragma unroll
    for (int p = 0; p < 4; p++) {
        int n = warpCol + p * 16 + b_noff;
        bBase[p] = smem_u + SM_B + (uint32_t)n * 512;
        bR7[p] = n & 7;
    }

    // ---- K loop: 16 steps of k=16 ----
#pragma unroll 2
    for (int ks = 0; ks < 16; ks++) {
        int kc = ks * 2;                         // base chunk
        uint32_t aF[2][4];
#pragma unroll
        for (int mt = 0; mt < 2; mt++)
            ldmatrix_x4(aF[mt], aBase[mt] + (uint32_t)(((kc + a_cadd) ^ aR7[mt]) << 4));
        uint32_t bF[4][4];
#pragma unroll
        for (int p = 0; p < 4; p++)
            ldmatrix_x4(bF[p], bBase[p] + (uint32_t)(((kc + b_cadd) ^ bR7[p]) << 4));
#pragma unroll
        for (int mt = 0; mt < 2; mt++)
#pragma unroll
            for (int nt = 0; nt < 8; nt++)
                mma_bf16(acc[mt][nt], aF[mt], &bF[nt >> 1][(nt & 1) * 2]);
    }

    // ---- dump accumulators to H (overwrites A/B region) ----
    __syncthreads();
    float* Hs = (float*)smem;
    int g = lane >> 2, tig = lane & 3;
#pragma unroll
    for (int mt = 0; mt < 2; mt++)
#pragma unroll
        for (int nt = 0; nt < 8; nt++) {
            int r0 = warpRow + mt * 16 + g;
            int c0 = warpCol + nt * 8 + tig * 2;
            Hs[r0 * H_STRIDE + c0]           = acc[mt][nt][0];
            Hs[r0 * H_STRIDE + c0 + 1]       = acc[mt][nt][1];
            Hs[(r0 + 8) * H_STRIDE + c0]     = acc[mt][nt][2];
            Hs[(r0 + 8) * H_STRIDE + c0 + 1] = acc[mt][nt][3];
        }
    __syncthreads();

    // ---- per-point epilogue + scatter: 2 threads per (row, batch) item ----
    int item = tid >> 1;                         // 0..255
    int half = tid & 1;
    int row = item & 127;
    int b = item >> 7;
    int gr = rowBase + row;
    bool live = (b < B) && (gr < Npts);

    float a0 = 0.f, a1 = 0.f, a2 = 0.f;
    if (live) {
        size_t gi = (size_t)b * Npts + gr;
        float vd0 = g_vdir[gi * 3 + 0];
        float vd1 = g_vdir[gi * 3 + 1];
        float vd2 = g_vdir[gi * 3 + 2];
        const float* Hrow = Hs + row * H_STRIDE;
        int j0 = half * 128;
#pragma unroll 8
        for (int jj = 0; jj < 128; jj++) {
            int j = j0 + jj;
            float h = Hrow[j] + b1s[j] + vd0 * w1v[j] + vd1 * w1v[256 + j] + vd2 * w1v[512 + j];
            h = fmaxf(h, 0.0f);
            a0 = fmaf(h, W2s[j], a0);
            a1 = fmaf(h, W2s[256 + j], a1);
            a2 = fmaf(h, W2s[512 + j], a2);
        }
    }
    a0 += __shfl_xor_sync(0xFFFFFFFFu, a0, 1);
    a1 += __shfl_xor_sync(0xFFFFFFFFu, a1, 1);
    a2 += __shfl_xor_sync(0xFFFFFFFFu, a2, 1);

    if (live && half == 0) {
        size_t gi = (size_t)b * Npts + gr;
        int id = g_idx[gi];
        if (id < HW) {
            float w = g_wts[gi];
            float r0 = sigmoidf_(a0 + b2g[0]);
            float r1 = sigmoidf_(a1 + b2g[1]);
            float r2 = sigmoidf_(a2 + b2g[2]);
            size_t base = (size_t)b * HW + id;
            atomicAdd(&g_num[base * 3 + 0], w * r0);
            atomicAdd(&g_num[base * 3 + 1], w * r1);
            atomicAdd(&g_num[base * 3 + 2], w * r2);
            atomicAdd(&g_den[base], w);
        }
    }
}

// ---------------- 6) composite -> output (B, 3, H, W) ----------------
__global__ void composite_kernel(const float* __restrict__ bkg,
                                 float* __restrict__ out, int B) {
    int i = blockIdx.x * blockDim.x + threadIdx.x;
    if (i >= B * HW) return;
    int b = i / HW, p = i - b * HW;
    float d = g_den[i];
    float alpha = 1.0f - expf(-d);
    float inv = __fdiv_rn(1.0f, d + 1e-8f);
#pragma unroll
    for (int c = 0; c < 3; c++) {
        float fg = g_num[(size_t)i * 3 + c] * inv;
        out[((size_t)b * 3 + c) * HW + p] = fg * alpha + bkg[c] * (1.0f - alpha);
    }
}

// ---------------- launch ----------------
extern "C" void kernel_launch(void* const* d_in, const int* in_sizes, int n_in,
                              void* d_out, int out_size) {
    const float* vert_pos = (const float*)d_in[0];
    const float* pose = (const float*)d_in[2];
    const float* intr = (const float*)d_in[3];
    const float* feat = (const float*)d_in[4];
    const float* opy  = (const float*)d_in[5];
    const float* W1   = (const float*)d_in[6];
    const float* b1   = (const float*)d_in[7];
    const float* W2   = (const float*)d_in[8];
    const float* b2   = (const float*)d_in[9];
    const float* bkg  = (const float*)d_in[10];
    float* out = (float*)d_out;

    int N = in_sizes[0] / 3;
    int B = in_sizes[2] / 16;
    if (N > MAXN) N = MAXN;
    if (B > MAXB) B = MAXB;

    cudaFuncSetAttribute(fused_gemm_kernel,
                         cudaFuncAttributeMaxDynamicSharedMemorySize, SM_TOTAL);

    prep_kernel<<<1, 32>>>(pose, B);
    zero_kernel<<<(B * HW * 3 + 255) / 256, 256>>>(B);
    convert_w1_kernel<<<(DFEAT * HID + 255) / 256, 256>>>(W1);
    geom_kernel<<<(B * N + 255) / 256, 256>>>(vert_pos, pose, intr, opy, N, B);

    int nblocks = (N + 127) / 128;
    fused_gemm_kernel<<<nblocks, 512, SM_TOTAL>>>(feat, W1, b1, W2, b2, N, B);

    composite_kernel<<<(B * HW + 255) / 256, 256>>>(bkg, out, B);
}

// round 7
// speedup vs baseline: 3.3194x; 1.4462x over previous
#include <cuda_runtime.h>
#include <cuda_bf16.h>
#include <math.h>
#include <cstdint>

#define MAXN 200000
#define MAXB 2
#define IMG_H 300
#define IMG_W 400
#define HW (IMG_H * IMG_W)
#define DFEAT 256
#define HID 256

// ---------------- scratch (static device globals; no allocation) ----------------
__device__ float g_vdir[(size_t)MAXB * MAXN * 3];
__device__ float g_wts[(size_t)MAXB * MAXN];
__device__ int   g_idx[(size_t)MAXB * MAXN];
__device__ float g_num[(size_t)MAXB * HW * 3];
__device__ float g_den[(size_t)MAXB * HW];
__device__ float g_pinv[MAXB * 16];
__device__ __nv_bfloat16 g_W1T[DFEAT * HID];   // W1T[n][k] = W1[k][n], bf16, K-major
__device__ int g_tilectr;                      // work-stealing tile counter

__device__ __forceinline__ float sigmoidf_(float x) {
    return 1.0f / (1.0f + expf(-x));
}

// No-FMA dot product — matches XLA fusion codegen. DO NOT TOUCH.
__device__ __forceinline__ float dot3_nofma(float a0, float a1, float a2,
                                            float x0, float x1, float x2) {
    float t0 = __fmul_rn(a0, x0);
    float t1 = __fmul_rn(a1, x1);
    float t2 = __fmul_rn(a2, x2);
    return __fadd_rn(__fadd_rn(t0, t1), t2);
}

__device__ __forceinline__ uint32_t smem_to_u32(const void* p) {
    uint32_t a;
    asm("{ .reg .u64 t; cvta.to.shared.u64 t, %1; cvt.u32.u64 %0, t; }" : "=r"(a) : "l"(p));
    return a;
}

// ---------------- 1) 4x4 pose inverse ----------------
__global__ void prep_kernel(const float* __restrict__ pose, int B) {
    int b = threadIdx.x;
    if (b >= B) return;
    float a[4][8];
    for (int r = 0; r < 4; r++)
        for (int c = 0; c < 4; c++) {
            a[r][c] = pose[b * 16 + r * 4 + c];
            a[r][4 + c] = (r == c) ? 1.0f : 0.0f;
        }
    for (int col = 0; col < 4; col++) {
        int piv = col;
        for (int r = col + 1; r < 4; r++)
            if (fabsf(a[r][col]) > fabsf(a[piv][col])) piv = r;
        if (piv != col)
            for (int c = 0; c < 8; c++) { float t = a[col][c]; a[col][c] = a[piv][c]; a[piv][c] = t; }
        float d = 1.0f / a[col][col];
        for (int c = 0; c < 8; c++) a[col][c] *= d;
        for (int r = 0; r < 4; r++) {
            if (r == col) continue;
            float f = a[r][col];
            for (int c = 0; c < 8; c++) a[r][c] -= f * a[col][c];
        }
    }
    for (int r = 0; r < 4; r++)
        for (int c = 0; c < 4; c++)
            g_pinv[b * 16 + r * 4 + c] = a[r][4 + c];
}

// ---------------- 2) zero accumulators + tile counter ----------------
__global__ void zero_kernel(int B) {
    int i = blockIdx.x * blockDim.x + threadIdx.x;
    if (i == 0) g_tilectr = 0;
    int n3 = B * HW * 3;
    int n1 = B * HW;
    if (i < n3) g_num[i] = 0.0f;
    if (i < n1) g_den[i] = 0.0f;
}

// ---------------- 2b) W1[0:256] -> bf16 transposed (K-major) ----------------
__global__ void convert_w1_kernel(const float* __restrict__ W1) {
    int i = blockIdx.x * blockDim.x + threadIdx.x;
    if (i >= DFEAT * HID) return;
    int k = i >> 8, n = i & 255;
    g_W1T[n * DFEAT + k] = __float2bfloat16(W1[k * HID + n]);
}

// ---------------- 3) geometry (exact arithmetic — passes at 9e-8) ----------------
__global__ void geom_kernel(const float* __restrict__ vert_pos,
                            const float* __restrict__ pose,
                            const float* __restrict__ intr,
                            const float* __restrict__ opy,
                            int N, int B) {
    int i = blockIdx.x * blockDim.x + threadIdx.x;
    if (i >= B * N) return;
    int b = i / N, n = i - b * N;

    float px = vert_pos[n], py = vert_pos[N + n], pz = vert_pos[2 * N + n];
    const float* P = pose + b * 16;
    float x = __fadd_rn(dot3_nofma(P[0], P[1], P[2],  px, py, pz), __fmul_rn(P[3],  1.0f));
    float y = __fadd_rn(dot3_nofma(P[4], P[5], P[6],  px, py, pz), __fmul_rn(P[7],  1.0f));
    float z = __fadd_rn(dot3_nofma(P[8], P[9], P[10], px, py, pz), __fmul_rn(P[11], 1.0f));

    const float* Km = intr + b * 9;
    float u_ = dot3_nofma(Km[0], Km[1], Km[2], x, y, z);
    float v_ = dot3_nofma(Km[3], Km[4], Km[5], x, y, z);
    float w_ = dot3_nofma(Km[6], Km[7], Km[8], x, y, z);

    bool em = fabsf(w_) < 0.01f;
    float zs = em ? 0.01f : w_;
    float su = em ? -1e6f : __fdiv_rn(u_, zs);
    float sv = em ? -1e6f : __fdiv_rn(v_, zs);
    float sz = em ? -1e6f : zs;

    float inorm = rsqrtf(x * x + y * y + z * z);
    float nx = x * inorm, ny = y * inorm, nz = z * inorm;
    const float* Pi = g_pinv + b * 16;
    g_vdir[(size_t)i * 3 + 0] = dot3_nofma(Pi[0], Pi[1], Pi[2],  nx, ny, nz);
    g_vdir[(size_t)i * 3 + 1] = dot3_nofma(Pi[4], Pi[5], Pi[6],  nx, ny, nz);
    g_vdir[(size_t)i * 3 + 2] = dot3_nofma(Pi[8], Pi[9], Pi[10], nx, ny, nz);

    int ix = (int)rintf(su);
    int iy = (int)rintf(sv);
    bool valid = (ix >= 0) && (ix < IMG_W) && (iy >= 0) && (iy < IMG_H) && (sz >= 1.0f);
    g_idx[i] = valid ? iy * IMG_W + ix : HW;
    float op = sigmoidf_(opy[n]);
    op = fminf(fmaxf(op, 0.0f), 1.0f);
    g_wts[i] = valid ? op : 0.0f;
}

// ============ 4) persistent fused HMMA GEMM + register epilogue + scatter =========
// Persistent CTA (work-stealing). B (W1T 256x256 bf16) loaded ONCE per CTA.
// Tile = 64 points x 256 hidden x K=256. 512 threads, warp grid 2(m) x 8(n),
// warp tile 32x32 = 2x4 mma.m16n8k16 per K-step (acc 32 regs).
// Epilogue directly on accumulator registers: h = relu(acc + b1 + vdir.w1v),
// partial W2 dots, quad-shfl reduce, smem rowacc atomics, then scatter.
#define TILE_ROWS 64
// SMEM byte offsets
#define SMB   0                      // B tile: 256 n-rows x 512B          = 131072
#define SMA   131072                 // A tile: 64 rows x 512B             = 32768
#define SMT   163840                 // 7 tables x 256 floats              = 7168
#define SMVD  171008                 // vdir  [2][64][3] floats            = 1536
#define SMW   172544                 // wts   [2][64]                      = 512
#define SMID  173056                 // idx   [2][64] int                  = 512
#define SMRA  173568                 // rowacc[2][64][3] floats            = 1536
#define SMTI  175104                 // shared tile index (int)            = 4
#define SM_TOTAL 175168

__device__ __forceinline__ void ldmatrix_x4(uint32_t* r, uint32_t addr) {
    asm volatile("ldmatrix.sync.aligned.m8n8.x4.shared.b16 {%0,%1,%2,%3}, [%4];"
                 : "=r"(r[0]), "=r"(r[1]), "=r"(r[2]), "=r"(r[3]) : "r"(addr));
}
__device__ __forceinline__ void mma_bf16(float* d, const uint32_t* a, const uint32_t* b) {
    asm volatile(
        "mma.sync.aligned.m16n8k16.row.col.f32.bf16.bf16.f32 "
        "{%0,%1,%2,%3}, {%4,%5,%6,%7}, {%8,%9}, {%0,%1,%2,%3};"
        : "+f"(d[0]), "+f"(d[1]), "+f"(d[2]), "+f"(d[3])
        : "r"(a[0]), "r"(a[1]), "r"(a[2]), "r"(a[3]), "r"(b[0]), "r"(b[1]));
}

__global__ __launch_bounds__(512, 1) void fused_gemm_kernel(
    const float* __restrict__ feat,
    const float* __restrict__ W1,
    const float* __restrict__ b1g,
    const float* __restrict__ W2g,
    const float* __restrict__ b2g,
    int Npts, int B, int ntiles)
{
    extern __shared__ char smem[];
    uint32_t smem_u = smem_to_u32(smem);
    int tid = threadIdx.x;
    int wid = tid >> 5;
    int lane = tid & 31;
    int g = lane >> 2;                 // row group within mma fragment
    int tig = lane & 3;                // col pair within mma fragment

    float* s_b1  = (float*)(smem + SMT);
    float* s_w0  = s_b1 + 256;
    float* s_w1  = s_w0 + 256;
    float* s_w2  = s_w1 + 256;
    float* s_W2a = s_w2 + 256;
    float* s_W2b = s_W2a + 256;
    float* s_W2c = s_W2b + 256;
    float* s_vd  = (float*)(smem + SMVD);    // [(b*64+r)*3 + c]
    float* s_wt  = (float*)(smem + SMW);     // [b*64+r]
    int*   s_id  = (int*)  (smem + SMID);    // [b*64+r]
    float* s_ra  = (float*)(smem + SMRA);    // [(b*64+r)*3 + c]
    int*   s_tile= (int*)  (smem + SMTI);

    // ---- load B tile ONCE: g_W1T 256(n) x 256(k) bf16, swizzled ----
    for (int it = tid; it < 8192; it += 512) {
        int n = it >> 5;
        int chunk = it & 31;
        uint4 v = *(const uint4*)(g_W1T + (size_t)n * DFEAT + (chunk << 3));
        uint32_t off = (uint32_t)n * 512 + (uint32_t)((chunk ^ (n & 7)) << 4);
        *(uint4*)(smem + SMB + off) = v;
    }
    // ---- tables (W2 staged TRANSPOSED: [HID,3] row-major -> channel-major) ----
    if (tid < 256) {
        s_b1[tid]  = b1g[tid];
        s_w0[tid]  = W1[(size_t)DFEAT * HID + tid];
        s_w1[tid]  = W1[(size_t)(DFEAT + 1) * HID + tid];
        s_w2[tid]  = W1[(size_t)(DFEAT + 2) * HID + tid];
        s_W2a[tid] = W2g[tid * 3 + 0];
        s_W2b[tid] = W2g[tid * 3 + 1];
        s_W2c[tid] = W2g[tid * 3 + 2];
    }
    float bb0 = b2g[0], bb1 = b2g[1], bb2 = b2g[2];

    // ---- warp tiling / ldmatrix addressing (validated in round 6) ----
    int warpRow = (wid >> 3) * 32;     // 0 or 32
    int warpCol = (wid & 7) * 32;      // 0..224
    int a_roff = (lane < 16) ? lane : (lane - 16);
    int a_cadd = (lane < 16) ? 0 : 1;
    uint32_t aBase[2]; int aR7[2];
#pragma unroll
    for (int mt = 0; mt < 2; mt++) {
        int r = warpRow + mt * 16 + a_roff;
        aBase[mt] = smem_u + SMA + (uint32_t)r * 512;
        aR7[mt] = r & 7;
    }
    int b_noff = (lane & 7) + ((lane >= 16) ? 8 : 0);
    int b_cadd = (lane >> 3) & 1;
    uint32_t bBase[2]; int bR7[2];
#pragma unroll
    for (int p = 0; p < 2; p++) {
        int n = warpCol + p * 16 + b_noff;
        bBase[p] = smem_u + SMB + (uint32_t)n * 512;
        bR7[p] = n & 7;
    }

    // ================= persistent tile loop (work stealing) =================
    while (true) {
        __syncthreads();                     // prev scatter done; tables/B ready
        if (tid == 0) *s_tile = atomicAdd(&g_tilectr, 1);
        __syncthreads();
        int tile = *s_tile;
        if (tile >= ntiles) break;
        int rowBase = tile * TILE_ROWS;

        // ---- stage A tile: 64 rows x 256 fp32 -> bf16 swizzled ----
#pragma unroll
        for (int i = 0; i < 8; i++) {
            int it = tid + i * 512;          // 0..4095 float4
            int row = it >> 6;
            int c4 = (it & 63) << 2;
            int gr = rowBase + row;
            float4 v = (gr < Npts) ? *(const float4*)(feat + (size_t)gr * DFEAT + c4)
                                   : make_float4(0.f, 0.f, 0.f, 0.f);
            __nv_bfloat162 p0 = __floats2bfloat162_rn(v.x, v.y);
            __nv_bfloat162 p1 = __floats2bfloat162_rn(v.z, v.w);
            uint32_t off = (uint32_t)row * 512
                         + (uint32_t)(((c4 >> 3) ^ (row & 7)) << 4)
                         + (uint32_t)((c4 & 4) << 1);
            *(__nv_bfloat162*)(smem + SMA + off)     = p0;
            *(__nv_bfloat162*)(smem + SMA + off + 4) = p1;
        }
        // ---- stage per-point data + zero rowacc ----
        if (tid < 128) {
            int b = tid >> 6, r = tid & 63;
            int gr = rowBase + r;
            bool lv = (b < B) && (gr < Npts);
            size_t gi = (size_t)b * Npts + gr;
            int o = b * 64 + r;
            s_vd[o * 3 + 0] = lv ? g_vdir[gi * 3 + 0] : 0.0f;
            s_vd[o * 3 + 1] = lv ? g_vdir[gi * 3 + 1] : 0.0f;
            s_vd[o * 3 + 2] = lv ? g_vdir[gi * 3 + 2] : 0.0f;
            s_wt[o] = lv ? g_wts[gi] : 0.0f;
            s_id[o] = lv ? g_idx[gi] : HW;
        } else {
            int q = tid - 128;
            if (q < 384) s_ra[q] = 0.0f;
        }
        __syncthreads();

        // ---- MMA: K=256 in 16 steps ----
        float acc[2][4][4];
#pragma unroll
        for (int mt = 0; mt < 2; mt++)
#pragma unroll
            for (int nt = 0; nt < 4; nt++)
#pragma unroll
                for (int e = 0; e < 4; e++) acc[mt][nt][e] = 0.0f;

#pragma unroll 4
        for (int ks = 0; ks < 16; ks++) {
            int kc = ks * 2;
            uint32_t aF[2][4];
#pragma unroll
            for (int mt = 0; mt < 2; mt++)
                ldmatrix_x4(aF[mt], aBase[mt] + (uint32_t)(((kc + a_cadd) ^ aR7[mt]) << 4));
            uint32_t bF[2][4];
#pragma unroll
            for (int p = 0; p < 2; p++)
                ldmatrix_x4(bF[p], bBase[p] + (uint32_t)(((kc + b_cadd) ^ bR7[p]) << 4));
#pragma unroll
            for (int mt = 0; mt < 2; mt++)
#pragma unroll
                for (int nt = 0; nt < 4; nt++)
                    mma_bf16(acc[mt][nt], aF[mt], &bF[nt >> 1][(nt & 1) * 2]);
        }

        // ---- register epilogue ----
        // acc[mt][nt][e]: row = warpRow + mt*16 + g + (e>=2)*8
        //                 col = warpCol + nt*8 + tig*2 + (e&1)
#pragma unroll
        for (int b = 0; b < MAXB; b++) {
#pragma unroll
            for (int mt = 0; mt < 2; mt++) {
#pragma unroll
                for (int hf = 0; hf < 2; hf++) {
                    int r = warpRow + mt * 16 + g + hf * 8;
                    int o = b * 64 + r;
                    float vd0 = s_vd[o * 3 + 0];
                    float vd1 = s_vd[o * 3 + 1];
                    float vd2 = s_vd[o * 3 + 2];
                    float p0 = 0.f, p1 = 0.f, p2 = 0.f;
#pragma unroll
                    for (int nt = 0; nt < 4; nt++) {
#pragma unroll
                        for (int e1 = 0; e1 < 2; e1++) {
                            int j = warpCol + nt * 8 + tig * 2 + e1;
                            float h = acc[mt][nt][hf * 2 + e1] + s_b1[j]
                                    + vd0 * s_w0[j] + vd1 * s_w1[j] + vd2 * s_w2[j];
                            h = fmaxf(h, 0.0f);
                            p0 = fmaf(h, s_W2a[j], p0);
                            p1 = fmaf(h, s_W2b[j], p1);
                            p2 = fmaf(h, s_W2c[j], p2);
                        }
                    }
                    // reduce across the 4 tig lanes of the quad
                    p0 += __shfl_xor_sync(0xFFFFFFFFu, p0, 1);
                    p0 += __shfl_xor_sync(0xFFFFFFFFu, p0, 2);
                    p1 += __shfl_xor_sync(0xFFFFFFFFu, p1, 1);
                    p1 += __shfl_xor_sync(0xFFFFFFFFu, p1, 2);
                    p2 += __shfl_xor_sync(0xFFFFFFFFu, p2, 1);
                    p2 += __shfl_xor_sync(0xFFFFFFFFu, p2, 2);
                    if (tig == 0) {
                        atomicAdd(&s_ra[o * 3 + 0], p0);
                        atomicAdd(&s_ra[o * 3 + 1], p1);
                        atomicAdd(&s_ra[o * 3 + 2], p2);
                    }
                }
            }
        }
        __syncthreads();

        // ---- scatter: one thread per (b, row) ----
        if (tid < 128) {
            int b = tid >> 6, r = tid & 63;
            int o = b * 64 + r;
            int id = s_id[o];
            if (id < HW) {
                float w = s_wt[o];
                float r0 = sigmoidf_(s_ra[o * 3 + 0] + bb0);
                float r1 = sigmoidf_(s_ra[o * 3 + 1] + bb1);
                float r2 = sigmoidf_(s_ra[o * 3 + 2] + bb2);
                size_t base = (size_t)b * HW + id;
                atomicAdd(&g_num[base * 3 + 0], w * r0);
                atomicAdd(&g_num[base * 3 + 1], w * r1);
                atomicAdd(&g_num[base * 3 + 2], w * r2);
                atomicAdd(&g_den[base], w);
            }
        }
    }
}

// ---------------- 6) composite -> output (B, 3, H, W) ----------------
__global__ void composite_kernel(const float* __restrict__ bkg,
                                 float* __restrict__ out, int B) {
    int i = blockIdx.x * blockDim.x + threadIdx.x;
    if (i >= B * HW) return;
    int b = i / HW, p = i - b * HW;
    float d = g_den[i];
    float alpha = 1.0f - expf(-d);
    float inv = __fdiv_rn(1.0f, d + 1e-8f);
#pragma unroll
    for (int c = 0; c < 3; c++) {
        float fg = g_num[(size_t)i * 3 + c] * inv;
        out[((size_t)b * 3 + c) * HW + p] = fg * alpha + bkg[c] * (1.0f - alpha);
    }
}

// ---------------- launch ----------------
extern "C" void kernel_launch(void* const* d_in, const int* in_sizes, int n_in,
                              void* d_out, int out_size) {
    const float* vert_pos = (const float*)d_in[0];
    const float* pose = (const float*)d_in[2];
    const float* intr = (const float*)d_in[3];
    const float* feat = (const float*)d_in[4];
    const float* opy  = (const float*)d_in[5];
    const float* W1   = (const float*)d_in[6];
    const float* b1   = (const float*)d_in[7];
    const float* W2   = (const float*)d_in[8];
    const float* b2   = (const float*)d_in[9];
    const float* bkg  = (const float*)d_in[10];
    float* out = (float*)d_out;

    int N = in_sizes[0] / 3;
    int B = in_sizes[2] / 16;
    if (N > MAXN) N = MAXN;
    if (B > MAXB) B = MAXB;

    cudaFuncSetAttribute(fused_gemm_kernel,
                         cudaFuncAttributeMaxDynamicSharedMemorySize, SM_TOTAL);

    prep_kernel<<<1, 32>>>(pose, B);
    zero_kernel<<<(B * HW * 3 + 255) / 256, 256>>>(B);
    convert_w1_kernel<<<(DFEAT * HID + 255) / 256, 256>>>(W1);
    geom_kernel<<<(B * N + 255) / 256, 256>>>(vert_pos, pose, intr, opy, N, B);

    int ntiles = (N + TILE_ROWS - 1) / TILE_ROWS;
    // persistent grid; work-stealing tolerates 148- or 152-SM parts
    fused_gemm_kernel<<<152, 512, SM_TOTAL>>>(feat, W1, b1, W2, b2, N, B, ntiles);

    composite_kernel<<<(B * HW + 255) / 256, 256>>>(bkg, out, B);
}

// round 8
// speedup vs baseline: 3.6162x; 1.0894x over previous
#include <cuda_runtime.h>
#include <cuda_bf16.h>
#include <math.h>
#include <cstdint>

#define MAXN 200000
#define MAXB 2
#define IMG_H 300
#define IMG_W 400
#define HW (IMG_H * IMG_W)
#define DFEAT 256
#define HID 256

// ---------------- scratch (static device globals; no allocation) ----------------
__device__ float g_vdir[(size_t)MAXB * MAXN * 3];
__device__ float g_wts[(size_t)MAXB * MAXN];
__device__ int   g_idx[(size_t)MAXB * MAXN];
__device__ float g_num[(size_t)MAXB * HW * 3];
__device__ float g_den[(size_t)MAXB * HW];
__device__ float g_pinv[MAXB * 16];
__device__ __nv_bfloat16 g_W1T[DFEAT * HID];   // W1T[n][k] = W1[k][n], bf16, K-major
__device__ int g_tilectr;                      // work-stealing tile counter

__device__ __forceinline__ float sigmoidf_(float x) {
    return 1.0f / (1.0f + expf(-x));
}

// No-FMA dot product — matches XLA fusion codegen. DO NOT TOUCH.
__device__ __forceinline__ float dot3_nofma(float a0, float a1, float a2,
                                            float x0, float x1, float x2) {
    float t0 = __fmul_rn(a0, x0);
    float t1 = __fmul_rn(a1, x1);
    float t2 = __fmul_rn(a2, x2);
    return __fadd_rn(__fadd_rn(t0, t1), t2);
}

__device__ __forceinline__ uint32_t smem_to_u32(const void* p) {
    uint32_t a;
    asm("{ .reg .u64 t; cvta.to.shared.u64 t, %1; cvt.u32.u64 %0, t; }" : "=r"(a) : "l"(p));
    return a;
}

// ---------------- 1) 4x4 pose inverse ----------------
__global__ void prep_kernel(const float* __restrict__ pose, int B) {
    int b = threadIdx.x;
    if (b >= B) return;
    float a[4][8];
    for (int r = 0; r < 4; r++)
        for (int c = 0; c < 4; c++) {
            a[r][c] = pose[b * 16 + r * 4 + c];
            a[r][4 + c] = (r == c) ? 1.0f : 0.0f;
        }
    for (int col = 0; col < 4; col++) {
        int piv = col;
        for (int r = col + 1; r < 4; r++)
            if (fabsf(a[r][col]) > fabsf(a[piv][col])) piv = r;
        if (piv != col)
            for (int c = 0; c < 8; c++) { float t = a[col][c]; a[col][c] = a[piv][c]; a[piv][c] = t; }
        float d = 1.0f / a[col][col];
        for (int c = 0; c < 8; c++) a[col][c] *= d;
        for (int r = 0; r < 4; r++) {
            if (r == col) continue;
            float f = a[r][col];
            for (int c = 0; c < 8; c++) a[r][c] -= f * a[col][c];
        }
    }
    for (int r = 0; r < 4; r++)
        for (int c = 0; c < 4; c++)
            g_pinv[b * 16 + r * 4 + c] = a[r][4 + c];
}

// ---------------- 2) zero accumulators + tile counter ----------------
__global__ void zero_kernel(int B) {
    int i = blockIdx.x * blockDim.x + threadIdx.x;
    if (i == 0) g_tilectr = 0;
    int n3 = B * HW * 3;
    int n1 = B * HW;
    if (i < n3) g_num[i] = 0.0f;
    if (i < n1) g_den[i] = 0.0f;
}

// ---------------- 2b) W1[0:256] -> bf16 transposed (K-major) ----------------
__global__ void convert_w1_kernel(const float* __restrict__ W1) {
    int i = blockIdx.x * blockDim.x + threadIdx.x;
    if (i >= DFEAT * HID) return;
    int k = i >> 8, n = i & 255;
    g_W1T[n * DFEAT + k] = __float2bfloat16(W1[k * HID + n]);
}

// ---------------- 3) geometry (exact arithmetic — passes at 9e-8) ----------------
__global__ void geom_kernel(const float* __restrict__ vert_pos,
                            const float* __restrict__ pose,
                            const float* __restrict__ intr,
                            const float* __restrict__ opy,
                            int N, int B) {
    int i = blockIdx.x * blockDim.x + threadIdx.x;
    if (i >= B * N) return;
    int b = i / N, n = i - b * N;

    float px = vert_pos[n], py = vert_pos[N + n], pz = vert_pos[2 * N + n];
    const float* P = pose + b * 16;
    float x = __fadd_rn(dot3_nofma(P[0], P[1], P[2],  px, py, pz), __fmul_rn(P[3],  1.0f));
    float y = __fadd_rn(dot3_nofma(P[4], P[5], P[6],  px, py, pz), __fmul_rn(P[7],  1.0f));
    float z = __fadd_rn(dot3_nofma(P[8], P[9], P[10], px, py, pz), __fmul_rn(P[11], 1.0f));

    const float* Km = intr + b * 9;
    float u_ = dot3_nofma(Km[0], Km[1], Km[2], x, y, z);
    float v_ = dot3_nofma(Km[3], Km[4], Km[5], x, y, z);
    float w_ = dot3_nofma(Km[6], Km[7], Km[8], x, y, z);

    bool em = fabsf(w_) < 0.01f;
    float zs = em ? 0.01f : w_;
    float su = em ? -1e6f : __fdiv_rn(u_, zs);
    float sv = em ? -1e6f : __fdiv_rn(v_, zs);
    float sz = em ? -1e6f : zs;

    float inorm = rsqrtf(x * x + y * y + z * z);
    float nx = x * inorm, ny = y * inorm, nz = z * inorm;
    const float* Pi = g_pinv + b * 16;
    g_vdir[(size_t)i * 3 + 0] = dot3_nofma(Pi[0], Pi[1], Pi[2],  nx, ny, nz);
    g_vdir[(size_t)i * 3 + 1] = dot3_nofma(Pi[4], Pi[5], Pi[6],  nx, ny, nz);
    g_vdir[(size_t)i * 3 + 2] = dot3_nofma(Pi[8], Pi[9], Pi[10], nx, ny, nz);

    int ix = (int)rintf(su);
    int iy = (int)rintf(sv);
    bool valid = (ix >= 0) && (ix < IMG_W) && (iy >= 0) && (iy < IMG_H) && (sz >= 1.0f);
    g_idx[i] = valid ? iy * IMG_W + ix : HW;
    float op = sigmoidf_(opy[n]);
    op = fminf(fmaxf(op, 0.0f), 1.0f);
    g_wts[i] = valid ? op : 0.0f;
}

// ============ 4) persistent fused HMMA GEMM + register epilogue + scatter =========
// Persistent CTA (work-stealing). B (W1T 256x256 bf16) loaded ONCE per CTA.
// Tile = 64 points x 256 hidden x K=256. 512 threads, warp grid 2(m) x 8(n),
// warp tile 32x32 = 2x4 mma.m16n8k16 per K-step (acc 32 regs).
// Epilogue j-OUTER: hoist table entries per j (7 LDS) and vd (24 LDS) —
// ~80 LDS/thread/tile instead of ~470 (round-7 bottleneck).
#define TILE_ROWS 64
// SMEM byte offsets
#define SMB   0                      // B tile: 256 n-rows x 512B          = 131072
#define SMA   131072                 // A tile: 64 rows x 512B             = 32768
#define SMT   163840                 // 7 tables x 256 floats              = 7168
#define SMVD  171008                 // vdir  [2][64][3] floats            = 1536
#define SMW   172544                 // wts   [2][64]                      = 512
#define SMID  173056                 // idx   [2][64] int                  = 512
#define SMRA  173568                 // rowacc[2][64][3] floats            = 1536
#define SMTI  175104                 // shared tile index (int)            = 4
#define SM_TOTAL 175168

__device__ __forceinline__ void ldmatrix_x4(uint32_t* r, uint32_t addr) {
    asm volatile("ldmatrix.sync.aligned.m8n8.x4.shared.b16 {%0,%1,%2,%3}, [%4];"
                 : "=r"(r[0]), "=r"(r[1]), "=r"(r[2]), "=r"(r[3]) : "r"(addr));
}
__device__ __forceinline__ void mma_bf16(float* d, const uint32_t* a, const uint32_t* b) {
    asm volatile(
        "mma.sync.aligned.m16n8k16.row.col.f32.bf16.bf16.f32 "
        "{%0,%1,%2,%3}, {%4,%5,%6,%7}, {%8,%9}, {%0,%1,%2,%3};"
        : "+f"(d[0]), "+f"(d[1]), "+f"(d[2]), "+f"(d[3])
        : "r"(a[0]), "r"(a[1]), "r"(a[2]), "r"(a[3]), "r"(b[0]), "r"(b[1]));
}

__global__ __launch_bounds__(512, 1) void fused_gemm_kernel(
    const float* __restrict__ feat,
    const float* __restrict__ W1,
    const float* __restrict__ b1g,
    const float* __restrict__ W2g,
    const float* __restrict__ b2g,
    int Npts, int B, int ntiles)
{
    extern __shared__ char smem[];
    uint32_t smem_u = smem_to_u32(smem);
    int tid = threadIdx.x;
    int wid = tid >> 5;
    int lane = tid & 31;
    int g = lane >> 2;                 // row group within mma fragment
    int tig = lane & 3;                // col pair within mma fragment

    float* s_b1  = (float*)(smem + SMT);
    float* s_w0  = s_b1 + 256;
    float* s_w1  = s_w0 + 256;
    float* s_w2  = s_w1 + 256;
    float* s_W2a = s_w2 + 256;
    float* s_W2b = s_W2a + 256;
    float* s_W2c = s_W2b + 256;
    float* s_vd  = (float*)(smem + SMVD);    // [(b*64+r)*3 + c]
    float* s_wt  = (float*)(smem + SMW);     // [b*64+r]
    int*   s_id  = (int*)  (smem + SMID);    // [b*64+r]
    float* s_ra  = (float*)(smem + SMRA);    // [(b*64+r)*3 + c]
    int*   s_tile= (int*)  (smem + SMTI);

    // ---- load B tile ONCE: g_W1T 256(n) x 256(k) bf16, swizzled ----
    for (int it = tid; it < 8192; it += 512) {
        int n = it >> 5;
        int chunk = it & 31;
        uint4 v = *(const uint4*)(g_W1T + (size_t)n * DFEAT + (chunk << 3));
        uint32_t off = (uint32_t)n * 512 + (uint32_t)((chunk ^ (n & 7)) << 4);
        *(uint4*)(smem + SMB + off) = v;
    }
    // ---- tables (W2 staged TRANSPOSED: [HID,3] row-major -> channel-major) ----
    if (tid < 256) {
        s_b1[tid]  = b1g[tid];
        s_w0[tid]  = W1[(size_t)DFEAT * HID + tid];
        s_w1[tid]  = W1[(size_t)(DFEAT + 1) * HID + tid];
        s_w2[tid]  = W1[(size_t)(DFEAT + 2) * HID + tid];
        s_W2a[tid] = W2g[tid * 3 + 0];
        s_W2b[tid] = W2g[tid * 3 + 1];
        s_W2c[tid] = W2g[tid * 3 + 2];
    }
    float bb0 = b2g[0], bb1 = b2g[1], bb2 = b2g[2];

    // ---- warp tiling / ldmatrix addressing (validated in rounds 6-7) ----
    int warpRow = (wid >> 3) * 32;     // 0 or 32
    int warpCol = (wid & 7) * 32;      // 0..224
    int a_roff = (lane < 16) ? lane : (lane - 16);
    int a_cadd = (lane < 16) ? 0 : 1;
    uint32_t aBase[2]; int aR7[2];
#pragma unroll
    for (int mt = 0; mt < 2; mt++) {
        int r = warpRow + mt * 16 + a_roff;
        aBase[mt] = smem_u + SMA + (uint32_t)r * 512;
        aR7[mt] = r & 7;
    }
    int b_noff = (lane & 7) + ((lane >= 16) ? 8 : 0);
    int b_cadd = (lane >> 3) & 1;
    uint32_t bBase[2]; int bR7[2];
#pragma unroll
    for (int p = 0; p < 2; p++) {
        int n = warpCol + p * 16 + b_noff;
        bBase[p] = smem_u + SMB + (uint32_t)n * 512;
        bR7[p] = n & 7;
    }

    // ================= persistent tile loop (work stealing) =================
    while (true) {
        __syncthreads();                     // prev scatter done; tables/B ready
        if (tid == 0) *s_tile = atomicAdd(&g_tilectr, 1);
        __syncthreads();
        int tile = *s_tile;
        if (tile >= ntiles) break;
        int rowBase = tile * TILE_ROWS;

        // ---- stage A tile: 64 rows x 256 fp32 -> bf16 swizzled ----
#pragma unroll
        for (int i = 0; i < 8; i++) {
            int it = tid + i * 512;          // 0..4095 float4
            int row = it >> 6;
            int c4 = (it & 63) << 2;
            int gr = rowBase + row;
            float4 v = (gr < Npts) ? *(const float4*)(feat + (size_t)gr * DFEAT + c4)
                                   : make_float4(0.f, 0.f, 0.f, 0.f);
            __nv_bfloat162 p0 = __floats2bfloat162_rn(v.x, v.y);
            __nv_bfloat162 p1 = __floats2bfloat162_rn(v.z, v.w);
            uint32_t off = (uint32_t)row * 512
                         + (uint32_t)(((c4 >> 3) ^ (row & 7)) << 4)
                         + (uint32_t)((c4 & 4) << 1);
            *(__nv_bfloat162*)(smem + SMA + off)     = p0;
            *(__nv_bfloat162*)(smem + SMA + off + 4) = p1;
        }
        // ---- stage per-point data + zero rowacc ----
        if (tid < 128) {
            int b = tid >> 6, r = tid & 63;
            int gr = rowBase + r;
            bool lv = (b < B) && (gr < Npts);
            size_t gi = (size_t)b * Npts + gr;
            int o = b * 64 + r;
            s_vd[o * 3 + 0] = lv ? g_vdir[gi * 3 + 0] : 0.0f;
            s_vd[o * 3 + 1] = lv ? g_vdir[gi * 3 + 1] : 0.0f;
            s_vd[o * 3 + 2] = lv ? g_vdir[gi * 3 + 2] : 0.0f;
            s_wt[o] = lv ? g_wts[gi] : 0.0f;
            s_id[o] = lv ? g_idx[gi] : HW;
        } else {
            int q = tid - 128;
            if (q < 384) s_ra[q] = 0.0f;
        }
        __syncthreads();

        // ---- MMA: K=256 in 16 steps ----
        float acc[2][4][4];
#pragma unroll
        for (int mt = 0; mt < 2; mt++)
#pragma unroll
            for (int nt = 0; nt < 4; nt++)
#pragma unroll
                for (int e = 0; e < 4; e++) acc[mt][nt][e] = 0.0f;

#pragma unroll 4
        for (int ks = 0; ks < 16; ks++) {
            int kc = ks * 2;
            uint32_t aF[2][4];
#pragma unroll
            for (int mt = 0; mt < 2; mt++)
                ldmatrix_x4(aF[mt], aBase[mt] + (uint32_t)(((kc + a_cadd) ^ aR7[mt]) << 4));
            uint32_t bF[2][4];
#pragma unroll
            for (int p = 0; p < 2; p++)
                ldmatrix_x4(bF[p], bBase[p] + (uint32_t)(((kc + b_cadd) ^ bR7[p]) << 4));
#pragma unroll
            for (int mt = 0; mt < 2; mt++)
#pragma unroll
                for (int nt = 0; nt < 4; nt++)
                    mma_bf16(acc[mt][nt], aF[mt], &bF[nt >> 1][(nt & 1) * 2]);
        }

        // ---- register epilogue, j-OUTER (hoisted tables + vd) ----
        // acc[mt][nt][e]: row = warpRow + mt*16 + g + (e>=2)*8
        //                 col = warpCol + nt*8 + tig*2 + (e&1)
        float vd[MAXB][2][2][3];             // [b][mt][hf][c] — 24 regs
#pragma unroll
        for (int b = 0; b < MAXB; b++)
#pragma unroll
            for (int mt = 0; mt < 2; mt++)
#pragma unroll
                for (int hf = 0; hf < 2; hf++) {
                    int r = warpRow + mt * 16 + g + hf * 8;
                    int o = b * 64 + r;
                    vd[b][mt][hf][0] = s_vd[o * 3 + 0];
                    vd[b][mt][hf][1] = s_vd[o * 3 + 1];
                    vd[b][mt][hf][2] = s_vd[o * 3 + 2];
                }
        float pacc[MAXB][2][2][3];           // [b][mt][hf][ch] — 24 regs
#pragma unroll
        for (int b = 0; b < MAXB; b++)
#pragma unroll
            for (int mt = 0; mt < 2; mt++)
#pragma unroll
                for (int hf = 0; hf < 2; hf++)
                    pacc[b][mt][hf][0] = pacc[b][mt][hf][1] = pacc[b][mt][hf][2] = 0.0f;

#pragma unroll
        for (int jj = 0; jj < 8; jj++) {
            int nt = jj >> 1, e1 = jj & 1;
            int j = warpCol + nt * 8 + tig * 2 + e1;
            float B1 = s_b1[j];
            float w0 = s_w0[j], w1 = s_w1[j], w2 = s_w2[j];
            float Wa = s_W2a[j], Wb = s_W2b[j], Wc = s_W2c[j];
#pragma unroll
            for (int b = 0; b < MAXB; b++)
#pragma unroll
                for (int mt = 0; mt < 2; mt++)
#pragma unroll
                    for (int hf = 0; hf < 2; hf++) {
                        float h = acc[mt][nt][hf * 2 + e1] + B1
                                + vd[b][mt][hf][0] * w0
                                + vd[b][mt][hf][1] * w1
                                + vd[b][mt][hf][2] * w2;
                        h = fmaxf(h, 0.0f);
                        pacc[b][mt][hf][0] = fmaf(h, Wa, pacc[b][mt][hf][0]);
                        pacc[b][mt][hf][1] = fmaf(h, Wb, pacc[b][mt][hf][1]);
                        pacc[b][mt][hf][2] = fmaf(h, Wc, pacc[b][mt][hf][2]);
                    }
        }

        // ---- quad reduce + rowacc atomics ----
#pragma unroll
        for (int b = 0; b < MAXB; b++)
#pragma unroll
            for (int mt = 0; mt < 2; mt++)
#pragma unroll
                for (int hf = 0; hf < 2; hf++) {
                    float p0 = pacc[b][mt][hf][0];
                    float p1 = pacc[b][mt][hf][1];
                    float p2 = pacc[b][mt][hf][2];
                    p0 += __shfl_xor_sync(0xFFFFFFFFu, p0, 1);
                    p0 += __shfl_xor_sync(0xFFFFFFFFu, p0, 2);
                    p1 += __shfl_xor_sync(0xFFFFFFFFu, p1, 1);
                    p1 += __shfl_xor_sync(0xFFFFFFFFu, p1, 2);
                    p2 += __shfl_xor_sync(0xFFFFFFFFu, p2, 1);
                    p2 += __shfl_xor_sync(0xFFFFFFFFu, p2, 2);
                    if (tig == 0) {
                        int r = warpRow + mt * 16 + g + hf * 8;
                        int o = b * 64 + r;
                        atomicAdd(&s_ra[o * 3 + 0], p0);
                        atomicAdd(&s_ra[o * 3 + 1], p1);
                        atomicAdd(&s_ra[o * 3 + 2], p2);
                    }
                }
        __syncthreads();

        // ---- scatter: one thread per (b, row) ----
        if (tid < 128) {
            int b = tid >> 6, r = tid & 63;
            int o = b * 64 + r;
            int id = s_id[o];
            if (id < HW) {
                float w = s_wt[o];
                float r0 = sigmoidf_(s_ra[o * 3 + 0] + bb0);
                float r1 = sigmoidf_(s_ra[o * 3 + 1] + bb1);
                float r2 = sigmoidf_(s_ra[o * 3 + 2] + bb2);
                size_t base = (size_t)b * HW + id;
                atomicAdd(&g_num[base * 3 + 0], w * r0);
                atomicAdd(&g_num[base * 3 + 1], w * r1);
                atomicAdd(&g_num[base * 3 + 2], w * r2);
                atomicAdd(&g_den[base], w);
            }
        }
    }
}

// ---------------- 6) composite -> output (B, 3, H, W) ----------------
__global__ void composite_kernel(const float* __restrict__ bkg,
                                 float* __restrict__ out, int B) {
    int i = blockIdx.x * blockDim.x + threadIdx.x;
    if (i >= B * HW) return;
    int b = i / HW, p = i - b * HW;
    float d = g_den[i];
    float alpha = 1.0f - expf(-d);
    float inv = __fdiv_rn(1.0f, d + 1e-8f);
#pragma unroll
    for (int c = 0; c < 3; c++) {
        float fg = g_num[(size_t)i * 3 + c] * inv;
        out[((size_t)b * 3 + c) * HW + p] = fg * alpha + bkg[c] * (1.0f - alpha);
    }
}

// ---------------- launch ----------------
extern "C" void kernel_launch(void* const* d_in, const int* in_sizes, int n_in,
                              void* d_out, int out_size) {
    const float* vert_pos = (const float*)d_in[0];
    const float* pose = (const float*)d_in[2];
    const float* intr = (const float*)d_in[3];
    const float* feat = (const float*)d_in[4];
    const float* opy  = (const float*)d_in[5];
    const float* W1   = (const float*)d_in[6];
    const float* b1   = (const float*)d_in[7];
    const float* W2   = (const float*)d_in[8];
    const float* b2   = (const float*)d_in[9];
    const float* bkg  = (const float*)d_in[10];
    float* out = (float*)d_out;

    int N = in_sizes[0] / 3;
    int B = in_sizes[2] / 16;
    if (N > MAXN) N = MAXN;
    if (B > MAXB) B = MAXB;

    cudaFuncSetAttribute(fused_gemm_kernel,
                         cudaFuncAttributeMaxDynamicSharedMemorySize, SM_TOTAL);

    prep_kernel<<<1, 32>>>(pose, B);
    zero_kernel<<<(B * HW * 3 + 255) / 256, 256>>>(B);
    convert_w1_kernel<<<(DFEAT * HID + 255) / 256, 256>>>(W1);
    geom_kernel<<<(B * N + 255) / 256, 256>>>(vert_pos, pose, intr, opy, N, B);

    int ntiles = (N + TILE_ROWS - 1) / TILE_ROWS;
    fused_gemm_kernel<<<152, 512, SM_TOTAL>>>(feat, W1, b1, W2, b2, N, B, ntiles);

    composite_kernel<<<(B * HW + 255) / 256, 256>>>(bkg, out, B);
}

// round 10
// speedup vs baseline: 4.0033x; 1.1070x over previous
#include <cuda_runtime.h>
#include <cuda_bf16.h>
#include <math.h>
#include <cstdint>

#define MAXN 200000
#define MAXB 2
#define IMG_H 300
#define IMG_W 400
#define HW (IMG_H * IMG_W)
#define DFEAT 256
#define HID 256

// ---------------- scratch (static device globals; no allocation) ----------------
__device__ float g_vdir[(size_t)MAXB * MAXN * 3];
__device__ float g_wts[(size_t)MAXB * MAXN];
__device__ int   g_idx[(size_t)MAXB * MAXN];
__device__ float g_num[(size_t)MAXB * HW * 3];
__device__ float g_den[(size_t)MAXB * HW];
__device__ float g_pinv[MAXB * 16];
__device__ __nv_bfloat16 g_W1T[DFEAT * HID];   // W1T[n][k] = W1[k][n], bf16, K-major

__device__ __forceinline__ float sigmoidf_(float x) {
    return 1.0f / (1.0f + expf(-x));
}

// No-FMA dot product — matches XLA fusion codegen. DO NOT TOUCH.
__device__ __forceinline__ float dot3_nofma(float a0, float a1, float a2,
                                            float x0, float x1, float x2) {
    float t0 = __fmul_rn(a0, x0);
    float t1 = __fmul_rn(a1, x1);
    float t2 = __fmul_rn(a2, x2);
    return __fadd_rn(__fadd_rn(t0, t1), t2);
}

__device__ __forceinline__ uint32_t smem_to_u32(const void* p) {
    uint32_t a;
    asm("{ .reg .u64 t; cvta.to.shared.u64 t, %1; cvt.u32.u64 %0, t; }" : "=r"(a) : "l"(p));
    return a;
}

// ---------------- 1) 4x4 pose inverse ----------------
__global__ void prep_kernel(const float* __restrict__ pose, int B) {
    int b = threadIdx.x;
    if (b >= B) return;
    float a[4][8];
    for (int r = 0; r < 4; r++)
        for (int c = 0; c < 4; c++) {
            a[r][c] = pose[b * 16 + r * 4 + c];
            a[r][4 + c] = (r == c) ? 1.0f : 0.0f;
        }
    for (int col = 0; col < 4; col++) {
        int piv = col;
        for (int r = col + 1; r < 4; r++)
            if (fabsf(a[r][col]) > fabsf(a[piv][col])) piv = r;
        if (piv != col)
            for (int c = 0; c < 8; c++) { float t = a[col][c]; a[col][c] = a[piv][c]; a[piv][c] = t; }
        float d = 1.0f / a[col][col];
        for (int c = 0; c < 8; c++) a[col][c] *= d;
        for (int r = 0; r < 4; r++) {
            if (r == col) continue;
            float f = a[r][col];
            for (int c = 0; c < 8; c++) a[r][c] -= f * a[col][c];
        }
    }
    for (int r = 0; r < 4; r++)
        for (int c = 0; c < 4; c++)
            g_pinv[b * 16 + r * 4 + c] = a[r][4 + c];
}

// ------- 2) init: zero accumulators + convert W1[0:256] -> bf16 K-major -------
__global__ void init_kernel(const float* __restrict__ W1, int B) {
    int i = blockIdx.x * blockDim.x + threadIdx.x;
    if (i < DFEAT * HID) {
        int k = i >> 8, n = i & 255;            // read coalesced over n
        g_W1T[n * DFEAT + k] = __float2bfloat16(W1[k * HID + n]);
    }
    int n3 = B * HW * 3;
    if (i < n3) g_num[i] = 0.0f;
    if (i < B * HW) g_den[i] = 0.0f;
}

// ---------------- 3) geometry (exact arithmetic — passes at 9e-8) ----------------
__global__ void geom_kernel(const float* __restrict__ vert_pos,
                            const float* __restrict__ pose,
                            const float* __restrict__ intr,
                            const float* __restrict__ opy,
                            int N, int B) {
    int i = blockIdx.x * blockDim.x + threadIdx.x;
    if (i >= B * N) return;
    int b = i / N, n = i - b * N;

    float px = vert_pos[n], py = vert_pos[N + n], pz = vert_pos[2 * N + n];
    const float* P = pose + b * 16;
    float x = __fadd_rn(dot3_nofma(P[0], P[1], P[2],  px, py, pz), __fmul_rn(P[3],  1.0f));
    float y = __fadd_rn(dot3_nofma(P[4], P[5], P[6],  px, py, pz), __fmul_rn(P[7],  1.0f));
    float z = __fadd_rn(dot3_nofma(P[8], P[9], P[10], px, py, pz), __fmul_rn(P[11], 1.0f));

    const float* Km = intr + b * 9;
    float u_ = dot3_nofma(Km[0], Km[1], Km[2], x, y, z);
    float v_ = dot3_nofma(Km[3], Km[4], Km[5], x, y, z);
    float w_ = dot3_nofma(Km[6], Km[7], Km[8], x, y, z);

    bool em = fabsf(w_) < 0.01f;
    float zs = em ? 0.01f : w_;
    float su = em ? -1e6f : __fdiv_rn(u_, zs);
    float sv = em ? -1e6f : __fdiv_rn(v_, zs);
    float sz = em ? -1e6f : zs;

    float inorm = rsqrtf(x * x + y * y + z * z);
    float nx = x * inorm, ny = y * inorm, nz = z * inorm;
    const float* Pi = g_pinv + b * 16;
    g_vdir[(size_t)i * 3 + 0] = dot3_nofma(Pi[0], Pi[1], Pi[2],  nx, ny, nz);
    g_vdir[(size_t)i * 3 + 1] = dot3_nofma(Pi[4], Pi[5], Pi[6],  nx, ny, nz);
    g_vdir[(size_t)i * 3 + 2] = dot3_nofma(Pi[8], Pi[9], Pi[10], nx, ny, nz);

    int ix = (int)rintf(su);
    int iy = (int)rintf(sv);
    bool valid = (ix >= 0) && (ix < IMG_W) && (iy >= 0) && (iy < IMG_H) && (sz >= 1.0f);
    g_idx[i] = valid ? iy * IMG_W + ix : HW;
    float op = sigmoidf_(opy[n]);
    op = fminf(fmaxf(op, 0.0f), 1.0f);
    g_wts[i] = valid ? op : 0.0f;
}

// ============ 4) persistent fused HMMA GEMM + register epilogue + scatter =========
// Deterministic tiles (tile = bid + wave*grid). 2 syncs/tile. Scatter overlaps
// with the NEXT tile's staging (disjoint SMEM; per-thread slot ownership).
#define TILE_ROWS 64
// SMEM byte offsets
#define SMB   0                      // B tile: 256 n-rows x 512B          = 131072
#define SMA   131072                 // A tile: 64 rows x 512B             = 32768
#define SMT1  163840                 // t1[256] float4 {b1,w0,w1,w2}       = 4096
#define SMT2  167936                 // t2[256] float4 {Wa,Wb,Wc,-}        = 4096
#define SMVD  172032                 // vdir  [2][64][3] floats            = 1536
#define SMW   173568                 // wts   [2][64]                      = 512
#define SMID  174080                 // idx   [2][64] int                  = 512
#define SMRA  174592                 // rowacc[2][64][3] floats            = 1536
#define SM_TOTAL 176128

__device__ __forceinline__ void ldmatrix_x4(uint32_t* r, uint32_t addr) {
    asm volatile("ldmatrix.sync.aligned.m8n8.x4.shared.b16 {%0,%1,%2,%3}, [%4];"
                 : "=r"(r[0]), "=r"(r[1]), "=r"(r[2]), "=r"(r[3]) : "r"(addr));
}
__device__ __forceinline__ void mma_bf16(float* d, const uint32_t* a, const uint32_t* b) {
    asm volatile(
        "mma.sync.aligned.m16n8k16.row.col.f32.bf16.bf16.f32 "
        "{%0,%1,%2,%3}, {%4,%5,%6,%7}, {%8,%9}, {%0,%1,%2,%3};"
        : "+f"(d[0]), "+f"(d[1]), "+f"(d[2]), "+f"(d[3])
        : "r"(a[0]), "r"(a[1]), "r"(a[2]), "r"(a[3]), "r"(b[0]), "r"(b[1]));
}

__global__ __launch_bounds__(512, 1) void fused_gemm_kernel(
    const float* __restrict__ feat,
    const float* __restrict__ W1,
    const float* __restrict__ b1g,
    const float* __restrict__ W2g,
    const float* __restrict__ b2g,
    int Npts, int B, int ntiles)
{
    extern __shared__ char smem[];
    uint32_t smem_u = smem_to_u32(smem);
    int tid = threadIdx.x;
    int wid = tid >> 5;
    int lane = tid & 31;
    int g = lane >> 2;                 // row group within mma fragment
    int tig = lane & 3;                // col pair within mma fragment

    float4* s_t1 = (float4*)(smem + SMT1);
    float4* s_t2 = (float4*)(smem + SMT2);
    float* s_vd  = (float*)(smem + SMVD);    // [(b*64+r)*3 + c]
    float* s_wt  = (float*)(smem + SMW);     // [b*64+r]
    int*   s_id  = (int*)  (smem + SMID);    // [b*64+r]
    float* s_ra  = (float*)(smem + SMRA);    // [(b*64+r)*3 + c]

    // ---- load B tile ONCE: g_W1T 256(n) x 256(k) bf16, swizzled ----
    for (int it = tid; it < 8192; it += 512) {
        int n = it >> 5;
        int chunk = it & 31;
        uint4 v = *(const uint4*)(g_W1T + (size_t)n * DFEAT + (chunk << 3));
        uint32_t off = (uint32_t)n * 512 + (uint32_t)((chunk ^ (n & 7)) << 4);
        *(uint4*)(smem + SMB + off) = v;
    }
    // ---- tables (packed float4; W2 TRANSPOSED: [HID,3] -> channel-major) ----
    if (tid < 256) {
        s_t1[tid] = make_float4(b1g[tid],
                                W1[(size_t)DFEAT * HID + tid],
                                W1[(size_t)(DFEAT + 1) * HID + tid],
                                W1[(size_t)(DFEAT + 2) * HID + tid]);
        s_t2[tid] = make_float4(W2g[tid * 3 + 0], W2g[tid * 3 + 1],
                                W2g[tid * 3 + 2], 0.0f);
    }
    // zero ALL 384 rowacc floats once (FIX of round-9 bug: old range tid>=256
    // only covered 256 of 384 entries). Scatter re-zeroes its slots per tile.
    if (tid < 384) s_ra[tid] = 0.0f;
    float bb0 = b2g[0], bb1 = b2g[1], bb2 = b2g[2];

    // ---- warp tiling / ldmatrix addressing (validated rounds 6-8) ----
    int warpRow = (wid >> 3) * 32;     // 0 or 32
    int warpCol = (wid & 7) * 32;      // 0..224
    int a_roff = (lane < 16) ? lane : (lane - 16);
    int a_cadd = (lane < 16) ? 0 : 1;
    uint32_t aBase[2]; int aR7[2];
#pragma unroll
    for (int mt = 0; mt < 2; mt++) {
        int r = warpRow + mt * 16 + a_roff;
        aBase[mt] = smem_u + SMA + (uint32_t)r * 512;
        aR7[mt] = r & 7;
    }
    int b_noff = (lane & 7) + ((lane >= 16) ? 8 : 0);
    int b_cadd = (lane >> 3) & 1;
    uint32_t bBase[2]; int bR7[2];
#pragma unroll
    for (int p = 0; p < 2; p++) {
        int n = warpCol + p * 16 + b_noff;
        bBase[p] = smem_u + SMB + (uint32_t)n * 512;
        bR7[p] = n & 7;
    }

    // ================= deterministic tile loop =================
    for (int tile = blockIdx.x; tile < ntiles; tile += gridDim.x) {
        int rowBase = tile * TILE_ROWS;

        // ---- stage A tile: 64 rows x 256 fp32 -> bf16 swizzled ----
        // (overlaps with the previous tile's scatter atomics — no sync above)
#pragma unroll
        for (int i = 0; i < 8; i++) {
            int it = tid + i * 512;          // 0..4095 float4
            int row = it >> 6;
            int c4 = (it & 63) << 2;
            int gr = rowBase + row;
            float4 v = (gr < Npts) ? *(const float4*)(feat + (size_t)gr * DFEAT + c4)
                                   : make_float4(0.f, 0.f, 0.f, 0.f);
            __nv_bfloat162 p0 = __floats2bfloat162_rn(v.x, v.y);
            __nv_bfloat162 p1 = __floats2bfloat162_rn(v.z, v.w);
            uint32_t off = (uint32_t)row * 512
                         + (uint32_t)(((c4 >> 3) ^ (row & 7)) << 4)
                         + (uint32_t)((c4 & 4) << 1);
            *(__nv_bfloat162*)(smem + SMA + off)     = p0;
            *(__nv_bfloat162*)(smem + SMA + off + 4) = p1;
        }
        // ---- stage per-point data (thread o owns slot o; also the scatter
        //      thread for slot o — program order protects vs prev scatter) ----
        if (tid < 128) {
            int b = tid >> 6, r = tid & 63;
            int gr = rowBase + r;
            bool lv = (b < B) && (gr < Npts);
            size_t gi = (size_t)b * Npts + gr;
            int o = tid;
            s_vd[o * 3 + 0] = lv ? g_vdir[gi * 3 + 0] : 0.0f;
            s_vd[o * 3 + 1] = lv ? g_vdir[gi * 3 + 1] : 0.0f;
            s_vd[o * 3 + 2] = lv ? g_vdir[gi * 3 + 2] : 0.0f;
            s_wt[o] = lv ? g_wts[gi] : 0.0f;
            s_id[o] = lv ? g_idx[gi] : HW;
        }
        __syncthreads();                     // A, pts, s_ra zeroing visible

        // ---- MMA: K=256 in 16 steps ----
        float acc[2][4][4];
#pragma unroll
        for (int mt = 0; mt < 2; mt++)
#pragma unroll
            for (int nt = 0; nt < 4; nt++)
#pragma unroll
                for (int e = 0; e < 4; e++) acc[mt][nt][e] = 0.0f;

#pragma unroll 4
        for (int ks = 0; ks < 16; ks++) {
            int kc = ks * 2;
            uint32_t aF[2][4];
#pragma unroll
            for (int mt = 0; mt < 2; mt++)
                ldmatrix_x4(aF[mt], aBase[mt] + (uint32_t)(((kc + a_cadd) ^ aR7[mt]) << 4));
            uint32_t bF[2][4];
#pragma unroll
            for (int p = 0; p < 2; p++)
                ldmatrix_x4(bF[p], bBase[p] + (uint32_t)(((kc + b_cadd) ^ bR7[p]) << 4));
#pragma unroll
            for (int mt = 0; mt < 2; mt++)
#pragma unroll
                for (int nt = 0; nt < 4; nt++)
                    mma_bf16(acc[mt][nt], aF[mt], &bF[nt >> 1][(nt & 1) * 2]);
        }

        // ---- register epilogue, j-outer, hoisted vd ----
        float vd[MAXB][2][2][3];
#pragma unroll
        for (int b = 0; b < MAXB; b++)
#pragma unroll
            for (int mt = 0; mt < 2; mt++)
#pragma unroll
                for (int hf = 0; hf < 2; hf++) {
                    int r = warpRow + mt * 16 + g + hf * 8;
                    int o = b * 64 + r;
                    vd[b][mt][hf][0] = s_vd[o * 3 + 0];
                    vd[b][mt][hf][1] = s_vd[o * 3 + 1];
                    vd[b][mt][hf][2] = s_vd[o * 3 + 2];
                }
        float pacc[MAXB][2][2][3];
#pragma unroll
        for (int b = 0; b < MAXB; b++)
#pragma unroll
            for (int mt = 0; mt < 2; mt++)
#pragma unroll
                for (int hf = 0; hf < 2; hf++)
                    pacc[b][mt][hf][0] = pacc[b][mt][hf][1] = pacc[b][mt][hf][2] = 0.0f;

#pragma unroll
        for (int jj = 0; jj < 8; jj++) {
            int nt = jj >> 1, e1 = jj & 1;
            int j = warpCol + nt * 8 + tig * 2 + e1;
            float4 t1 = s_t1[j];                 // {b1, w0, w1, w2}
            float4 t2 = s_t2[j];                 // {Wa, Wb, Wc, -}
#pragma unroll
            for (int b = 0; b < MAXB; b++)
#pragma unroll
                for (int mt = 0; mt < 2; mt++)
#pragma unroll
                    for (int hf = 0; hf < 2; hf++) {
                        float h = acc[mt][nt][hf * 2 + e1] + t1.x
                                + vd[b][mt][hf][0] * t1.y
                                + vd[b][mt][hf][1] * t1.z
                                + vd[b][mt][hf][2] * t1.w;
                        h = fmaxf(h, 0.0f);
                        pacc[b][mt][hf][0] = fmaf(h, t2.x, pacc[b][mt][hf][0]);
                        pacc[b][mt][hf][1] = fmaf(h, t2.y, pacc[b][mt][hf][1]);
                        pacc[b][mt][hf][2] = fmaf(h, t2.z, pacc[b][mt][hf][2]);
                    }
        }

        // ---- quad reduce + rowacc atomics ----
#pragma unroll
        for (int b = 0; b < MAXB; b++)
#pragma unroll
            for (int mt = 0; mt < 2; mt++)
#pragma unroll
                for (int hf = 0; hf < 2; hf++) {
                    float p0 = pacc[b][mt][hf][0];
                    float p1 = pacc[b][mt][hf][1];
                    float p2 = pacc[b][mt][hf][2];
                    p0 += __shfl_xor_sync(0xFFFFFFFFu, p0, 1);
                    p0 += __shfl_xor_sync(0xFFFFFFFFu, p0, 2);
                    p1 += __shfl_xor_sync(0xFFFFFFFFu, p1, 1);
                    p1 += __shfl_xor_sync(0xFFFFFFFFu, p1, 2);
                    p2 += __shfl_xor_sync(0xFFFFFFFFu, p2, 1);
                    p2 += __shfl_xor_sync(0xFFFFFFFFu, p2, 2);
                    if (tig == 0) {
                        int r = warpRow + mt * 16 + g + hf * 8;
                        int o = b * 64 + r;
                        atomicAdd(&s_ra[o * 3 + 0], p0);
                        atomicAdd(&s_ra[o * 3 + 1], p1);
                        atomicAdd(&s_ra[o * 3 + 2], p2);
                    }
                }
        __syncthreads();                     // s_ra complete

        // ---- scatter (thread o owns slot o); zero own s_ra for next tile ----
        if (tid < 128) {
            int b = tid >> 6;
            int o = tid;
            int id = s_id[o];
            float r0a = s_ra[o * 3 + 0];
            float r1a = s_ra[o * 3 + 1];
            float r2a = s_ra[o * 3 + 2];
            s_ra[o * 3 + 0] = 0.0f;
            s_ra[o * 3 + 1] = 0.0f;
            s_ra[o * 3 + 2] = 0.0f;
            if (id < HW) {
                float w = s_wt[o];
                float r0 = sigmoidf_(r0a + bb0);
                float r1 = sigmoidf_(r1a + bb1);
                float r2 = sigmoidf_(r2a + bb2);
                size_t base = (size_t)b * HW + id;
                atomicAdd(&g_num[base * 3 + 0], w * r0);
                atomicAdd(&g_num[base * 3 + 1], w * r1);
                atomicAdd(&g_num[base * 3 + 2], w * r2);
                atomicAdd(&g_den[base], w);
            }
        }
        // no sync here: next staging only touches SMA (all threads) and
        // per-point slots owned by the same thread that just read them.
    }
}

// ---------------- 6) composite -> output (B, 3, H, W) ----------------
__global__ void composite_kernel(const float* __restrict__ bkg,
                                 float* __restrict__ out, int B) {
    int i = blockIdx.x * blockDim.x + threadIdx.x;
    if (i >= B * HW) return;
    int b = i / HW, p = i - b * HW;
    float d = g_den[i];
    float alpha = 1.0f - expf(-d);
    float inv = __fdiv_rn(1.0f, d + 1e-8f);
#pragma unroll
    for (int c = 0; c < 3; c++) {
        float fg = g_num[(size_t)i * 3 + c] * inv;
        out[((size_t)b * 3 + c) * HW + p] = fg * alpha + bkg[c] * (1.0f - alpha);
    }
}

// ---------------- launch ----------------
extern "C" void kernel_launch(void* const* d_in, const int* in_sizes, int n_in,
                              void* d_out, int out_size) {
    const float* vert_pos = (const float*)d_in[0];
    const float* pose = (const float*)d_in[2];
    const float* intr = (const float*)d_in[3];
    const float* feat = (const float*)d_in[4];
    const float* opy  = (const float*)d_in[5];
    const float* W1   = (const float*)d_in[6];
    const float* b1   = (const float*)d_in[7];
    const float* W2   = (const float*)d_in[8];
    const float* b2   = (const float*)d_in[9];
    const float* bkg  = (const float*)d_in[10];
    float* out = (float*)d_out;

    int N = in_sizes[0] / 3;
    int B = in_sizes[2] / 16;
    if (N > MAXN) N = MAXN;
    if (B > MAXB) B = MAXB;

    cudaFuncSetAttribute(fused_gemm_kernel,
                         cudaFuncAttributeMaxDynamicSharedMemorySize, SM_TOTAL);

    prep_kernel<<<1, 32>>>(pose, B);
    init_kernel<<<(B * HW * 3 + 255) / 256, 256>>>(W1, B);
    geom_kernel<<<(B * N + 255) / 256, 256>>>(vert_pos, pose, intr, opy, N, B);

    int ntiles = (N + TILE_ROWS - 1) / TILE_ROWS;
    fused_gemm_kernel<<<152, 512, SM_TOTAL>>>(feat, W1, b1, W2, b2, N, B, ntiles);

    composite_kernel<<<(B * HW + 255) / 256, 256>>>(bkg, out, B);
}